// round 1
// baseline (speedup 1.0000x reference)
#include <cuda_runtime.h>
#include <stdint.h>

// FullPairwise (non-PBC): outputs concatenated as float32:
//   [0          , 2*MP)  atom_index12  (row0 = i + m*N, row1 = j + m*N)
//   [2*MP       , 5*MP)  shift_values  (all zeros)
//   [5*MP       , 6*MP)  mask          (d2 <= cutoff^2, as 0.0/1.0)
// where MP = M * P, P = N*(N-1)/2, pairs in jnp.triu_indices(N, k=1) order:
// row-major over i, j = i+1..N-1.

__global__ void fullpairwise_kernel(const int* __restrict__ species,
                                    const float* __restrict__ coords,
                                    float* __restrict__ out,
                                    int M, int N, long long P, long long MP,
                                    float c2) {
    // One block per (m, i) row of the upper triangle.
    int bid = blockIdx.x;
    int i = bid % (N - 1);
    int m = bid / (N - 1);

    // pairs before row i: i*(N-1) - i*(i-1)/2 ; row length L = N-1-i
    long long rowstart = (long long)i * (N - 1) - ((long long)i * (i - 1)) / 2;
    int L = N - 1 - i;

    const float* cm = coords + (size_t)m * N * 3;
    const int* sm = species + (size_t)m * N;

    float xi = cm[3 * i + 0];
    float yi = cm[3 * i + 1];
    float zi = cm[3 * i + 2];
    bool vi = (sm[i] != -1);

    long long base = (long long)m * P + rowstart;
    float* __restrict__ out_i    = out + base;
    float* __restrict__ out_j    = out + MP + base;
    float* __restrict__ out_mask = out + 5 * MP + base;

    int moff = m * N;
    float fi = (float)(i + moff);

    for (int t = threadIdx.x; t < L; t += blockDim.x) {
        int j = i + 1 + t;
        float xj = cm[3 * j + 0];
        float yj = cm[3 * j + 1];
        float zj = cm[3 * j + 2];

        // Forbid FMA contraction so rounding matches the elementwise reference
        // exactly at the cutoff boundary.
        float dx = __fsub_rn(xi, xj);
        float dy = __fsub_rn(yi, yj);
        float dz = __fsub_rn(zi, zj);
        float d2 = __fadd_rn(__fadd_rn(__fmul_rn(dx, dx), __fmul_rn(dy, dy)),
                             __fmul_rn(dz, dz));

        bool valid = vi && (sm[j] != -1);
        float mk = (valid && (d2 <= c2)) ? 1.0f : 0.0f;

        out_i[t]    = fi;
        out_j[t]    = (float)(j + moff);
        out_mask[t] = mk;
    }
}

extern "C" void kernel_launch(void* const* d_in, const int* in_sizes, int n_in,
                              void* d_out, int out_size) {
    const int*   species = (const int*)d_in[0];
    const float* coords  = (const float*)d_in[1];
    // d_in[2] = cell (unused, non-PBC), d_in[3] = pbc (all false)
    float* out = (float*)d_out;

    long long MN = in_sizes[0];               // M * N
    long long Nm1 = (long long)out_size / (3 * MN);  // out_size = 3*M*N*(N-1)
    int N = (int)Nm1 + 1;
    int M = (int)(MN / N);
    long long P  = (long long)N * (N - 1) / 2;
    long long MP = (long long)M * P;

    // shift_values region is all zeros: graph-capturable memset node.
    cudaMemsetAsync(out + 2 * MP, 0, (size_t)(3 * MP) * sizeof(float));

    const float c = 5.2f;
    int blocks = M * (N - 1);
    fullpairwise_kernel<<<blocks, 256>>>(species, coords, out, M, N, P, MP, c * c);
}

// round 4
// speedup vs baseline: 1.0595x; 1.0595x over previous
#include <cuda_runtime.h>
#include <stdint.h>

// FullPairwise (non-PBC), output float32 concat:
//   [0    , 2MP)  atom_index12  (row0 = i + m*N, row1 = j + m*N)
//   [2MP  , 5MP)  shift_values  (zeros, shape [MP,3] row-major)
//   [5MP  , 6MP)  mask          (d2 <= cutoff^2 as 0/1; NaN coords -> 0)
// MP = M*P, P = N*(N-1)/2, triu(k=1) row-major pair order.

#define MAX_ATOMS 16384
__device__ float4 g_coords4[MAX_ATOMS];

__global__ void pack_coords(const int* __restrict__ species,
                            const float* __restrict__ coords, int total) {
    int a = blockIdx.x * blockDim.x + threadIdx.x;
    if (a < total) {
        float x = coords[3 * a + 0];
        float y = coords[3 * a + 1];
        float z = coords[3 * a + 2];
        if (species[a] == -1) {
            x = __int_as_float(0x7fc00000);  // NaN -> mask false, matches ref
            y = x; z = x;
        }
        g_coords4[a] = make_float4(x, y, z, 0.0f);
    }
}

__global__ void __launch_bounds__(256)
fullpairwise_kernel(float* __restrict__ out,
                    int N, long long P, long long MP, float c2) {
    int bid = blockIdx.x;
    int i = bid % (N - 1);
    int m = bid / (N - 1);

    long long rowstart = (long long)i * (N - 1) - ((long long)i * (i - 1)) / 2;
    int L = N - 1 - i;                       // pairs in this row
    long long base = (long long)m * P + rowstart;

    const float4* __restrict__ cm4 = g_coords4 + (size_t)m * N;
    float4 ci = cm4[i];

    int moff = m * N;
    float fi = (float)(i + moff);
    int tx = threadIdx.x, bs = blockDim.x;

    // ---- region 1: idx row0, constant fi, len L at [base) ----
    {
        long long b = base;
        int h = (int)((4 - (b & 3)) & 3); if (h > L) h = L;
        for (int t = tx; t < h; t += bs) out[b + t] = fi;
        int nv = (L - h) >> 2;
        float4* vp = (float4*)(out + b + h);
        float4 v = make_float4(fi, fi, fi, fi);
        for (int k = tx; k < nv; k += bs) vp[k] = v;
        for (int t = h + 4 * nv + tx; t < L; t += bs) out[b + t] = fi;
    }
    // ---- region 2: idx row1, linear (i+1+t+moff), len L at [MP+base) ----
    {
        long long b = MP + base;
        float f0 = (float)(i + 1 + moff);
        int h = (int)((4 - (b & 3)) & 3); if (h > L) h = L;
        for (int t = tx; t < h; t += bs) out[b + t] = f0 + (float)t;
        int nv = (L - h) >> 2;
        float4* vp = (float4*)(out + b + h);
        for (int k = tx; k < nv; k += bs) {
            float f = f0 + (float)(h + 4 * k);
            vp[k] = make_float4(f, f + 1.0f, f + 2.0f, f + 3.0f);
        }
        for (int t = h + 4 * nv + tx; t < L; t += bs) out[b + t] = f0 + (float)t;
    }
    // ---- region 3: zeros, len 3L at [2MP + 3*base) ----
    {
        long long b = 2 * MP + 3 * base;
        int len = 3 * L;
        int h = (int)((4 - (b & 3)) & 3); if (h > len) h = len;
        for (int t = tx; t < h; t += bs) out[b + t] = 0.0f;
        int nv = (len - h) >> 2;
        float4* vp = (float4*)(out + b + h);
        float4 z = make_float4(0.f, 0.f, 0.f, 0.f);
        for (int k = tx; k < nv; k += bs) vp[k] = z;
        for (int t = h + 4 * nv + tx; t < len; t += bs) out[b + t] = 0.0f;
    }
    // ---- region 4: mask, len L at [5MP + base) ----
    {
        long long b = 5 * MP + base;
        int h = (int)((4 - (b & 3)) & 3); if (h > L) h = L;
        for (int t = tx; t < h; t += bs) {
            float4 cj = cm4[i + 1 + t];
            float dx = __fsub_rn(ci.x, cj.x);
            float dy = __fsub_rn(ci.y, cj.y);
            float dz = __fsub_rn(ci.z, cj.z);
            float d2 = __fadd_rn(__fadd_rn(__fmul_rn(dx, dx), __fmul_rn(dy, dy)),
                                 __fmul_rn(dz, dz));
            out[b + t] = (d2 <= c2) ? 1.0f : 0.0f;
        }
        int nv = (L - h) >> 2;
        float4* vp = (float4*)(out + b + h);
        for (int k = tx; k < nv; k += bs) {
            int j = i + 1 + h + 4 * k;
            float4 c0 = cm4[j], c1 = cm4[j + 1], c2v = cm4[j + 2], c3 = cm4[j + 3];
            float4 r;
            {
                float dx = __fsub_rn(ci.x, c0.x), dy = __fsub_rn(ci.y, c0.y), dz = __fsub_rn(ci.z, c0.z);
                float d2 = __fadd_rn(__fadd_rn(__fmul_rn(dx, dx), __fmul_rn(dy, dy)), __fmul_rn(dz, dz));
                r.x = (d2 <= c2) ? 1.0f : 0.0f;
            }
            {
                float dx = __fsub_rn(ci.x, c1.x), dy = __fsub_rn(ci.y, c1.y), dz = __fsub_rn(ci.z, c1.z);
                float d2 = __fadd_rn(__fadd_rn(__fmul_rn(dx, dx), __fmul_rn(dy, dy)), __fmul_rn(dz, dz));
                r.y = (d2 <= c2) ? 1.0f : 0.0f;
            }
            {
                float dx = __fsub_rn(ci.x, c2v.x), dy = __fsub_rn(ci.y, c2v.y), dz = __fsub_rn(ci.z, c2v.z);
                float d2 = __fadd_rn(__fadd_rn(__fmul_rn(dx, dx), __fmul_rn(dy, dy)), __fmul_rn(dz, dz));
                r.z = (d2 <= c2) ? 1.0f : 0.0f;
            }
            {
                float dx = __fsub_rn(ci.x, c3.x), dy = __fsub_rn(ci.y, c3.y), dz = __fsub_rn(ci.z, c3.z);
                float d2 = __fadd_rn(__fadd_rn(__fmul_rn(dx, dx), __fmul_rn(dy, dy)), __fmul_rn(dz, dz));
                r.w = (d2 <= c2) ? 1.0f : 0.0f;
            }
            vp[k] = r;
        }
        for (int t = h + 4 * nv + tx; t < L; t += bs) {
            float4 cj = cm4[i + 1 + t];
            float dx = __fsub_rn(ci.x, cj.x);
            float dy = __fsub_rn(ci.y, cj.y);
            float dz = __fsub_rn(ci.z, cj.z);
            float d2 = __fadd_rn(__fadd_rn(__fmul_rn(dx, dx), __fmul_rn(dy, dy)),
                                 __fmul_rn(dz, dz));
            out[b + t] = (d2 <= c2) ? 1.0f : 0.0f;
        }
    }
}

extern "C" void kernel_launch(void* const* d_in, const int* in_sizes, int n_in,
                              void* d_out, int out_size) {
    const int*   species = (const int*)d_in[0];
    const float* coords  = (const float*)d_in[1];
    float* out = (float*)d_out;

    long long MN = in_sizes[0];                        // M * N
    long long Nm1 = (long long)out_size / (3 * MN);    // out_size = 3*M*N*(N-1)
    int N = (int)Nm1 + 1;
    int M = (int)(MN / N);
    long long P  = (long long)N * (N - 1) / 2;
    long long MP = (long long)M * P;

    int total = (int)MN;
    pack_coords<<<(total + 255) / 256, 256>>>(species, coords, total);

    const float c = 5.2f;
    int blocks = M * (N - 1);
    fullpairwise_kernel<<<blocks, 256>>>(out, N, P, MP, c * c);
}

// round 7
// speedup vs baseline: 1.0928x; 1.0314x over previous
#include <cuda_runtime.h>
#include <stdint.h>

// FullPairwise (non-PBC), output float32 concat:
//   [0    , 2MP)  atom_index12  (row0 = i + m*N, row1 = j + m*N)
//   [2MP  , 5MP)  shift_values  (zeros, [MP,3])
//   [5MP  , 6MP)  mask          (d2 <= cutoff^2 as 0/1; NaN coords -> 0)
// MP = M*P, P = N*(N-1)/2, triu(k=1) row-major pair order.
//
// Load balance: rows i and N-2-i have lengths (N-1-i) and (i+1) -> exactly N
// pairs per block. Every block does identical work.

#define MAX_ATOMS 16384
__device__ float4 g_coords4[MAX_ATOMS];

__global__ void pack_coords(const int* __restrict__ species,
                            const float* __restrict__ coords, int total) {
    int a = blockIdx.x * blockDim.x + threadIdx.x;
    if (a < total) {
        float x = coords[3 * a + 0];
        float y = coords[3 * a + 1];
        float z = coords[3 * a + 2];
        if (species[a] == -1) {
            x = __int_as_float(0x7fc00000);  // NaN -> mask false (matches ref)
            y = x; z = x;
        }
        g_coords4[a] = make_float4(x, y, z, 0.0f);
    }
}

__device__ __forceinline__ void fill_const(float* __restrict__ out, long long b,
                                           int len, float v, int tx, int bs) {
    int h = (int)((4 - (b & 3)) & 3); if (h > len) h = len;
    for (int t = tx; t < h; t += bs) out[b + t] = v;
    int nv = (len - h) >> 2;
    float4* vp = (float4*)(out + b + h);
    float4 v4 = make_float4(v, v, v, v);
    #pragma unroll 4
    for (int k = tx; k < nv; k += bs) vp[k] = v4;
    for (int t = h + 4 * nv + tx; t < len; t += bs) out[b + t] = v;
}

__device__ __forceinline__ void fill_linear(float* __restrict__ out, long long b,
                                            int len, float f0, int tx, int bs) {
    int h = (int)((4 - (b & 3)) & 3); if (h > len) h = len;
    for (int t = tx; t < h; t += bs) out[b + t] = f0 + (float)t;
    int nv = (len - h) >> 2;
    float4* vp = (float4*)(out + b + h);
    #pragma unroll 4
    for (int k = tx; k < nv; k += bs) {
        float f = f0 + (float)(h + 4 * k);
        vp[k] = make_float4(f, f + 1.0f, f + 2.0f, f + 3.0f);
    }
    for (int t = h + 4 * nv + tx; t < len; t += bs) out[b + t] = f0 + (float)t;
}

__device__ __forceinline__ float mask1(float4 ci, float4 cj, float c2) {
    float dx = __fsub_rn(ci.x, cj.x);
    float dy = __fsub_rn(ci.y, cj.y);
    float dz = __fsub_rn(ci.z, cj.z);
    float d2 = __fadd_rn(__fadd_rn(__fmul_rn(dx, dx), __fmul_rn(dy, dy)),
                         __fmul_rn(dz, dz));
    return (d2 <= c2) ? 1.0f : 0.0f;
}

__device__ __forceinline__ void fill_mask(float* __restrict__ out, long long b,
                                          int len, const float4* __restrict__ cm4,
                                          int i, float4 ci, float c2,
                                          int tx, int bs) {
    int h = (int)((4 - (b & 3)) & 3); if (h > len) h = len;
    for (int t = tx; t < h; t += bs)
        out[b + t] = mask1(ci, cm4[i + 1 + t], c2);
    int nv = (len - h) >> 2;
    float4* vp = (float4*)(out + b + h);
    #pragma unroll 2
    for (int k = tx; k < nv; k += bs) {
        int j = i + 1 + h + 4 * k;
        float4 c0 = cm4[j], c1 = cm4[j + 1], c2v = cm4[j + 2], c3 = cm4[j + 3];
        float4 r;
        r.x = mask1(ci, c0, c2);
        r.y = mask1(ci, c1, c2);
        r.z = mask1(ci, c2v, c2);
        r.w = mask1(ci, c3, c2);
        vp[k] = r;
    }
    for (int t = h + 4 * nv + tx; t < len; t += bs)
        out[b + t] = mask1(ci, cm4[i + 1 + t], c2);
}

__device__ __forceinline__ void do_row(float* __restrict__ out, int m, int i,
                                       int N, long long P, long long MP,
                                       float c2, int tx, int bs) {
    long long rowstart = (long long)i * (N - 1) - ((long long)i * (i - 1)) / 2;
    int L = N - 1 - i;
    long long base = (long long)m * P + rowstart;
    const float4* __restrict__ cm4 = g_coords4 + (size_t)m * N;
    float4 ci = cm4[i];
    int moff = m * N;

    fill_const (out, base,               L,     (float)(i + moff),     tx, bs);
    fill_linear(out, MP + base,          L,     (float)(i + 1 + moff), tx, bs);
    fill_const (out, 2 * MP + 3 * base,  3 * L, 0.0f,                  tx, bs);
    fill_mask  (out, 5 * MP + base,      L,     cm4, i, ci, c2,        tx, bs);
}

__global__ void __launch_bounds__(256)
fullpairwise_kernel(float* __restrict__ out,
                    int N, int bpm, long long P, long long MP, float c2) {
    int bid = blockIdx.x;
    int b = bid % bpm;           // paired-row slot within molecule
    int m = bid / bpm;
    int R = N - 1;               // number of triu rows
    int r1 = b;
    int r2 = R - 1 - b;

    int tx = threadIdx.x, bs = blockDim.x;
    do_row(out, m, r1, N, P, MP, c2, tx, bs);
    if (r2 > r1)
        do_row(out, m, r2, N, P, MP, c2, tx, bs);
}

extern "C" void kernel_launch(void* const* d_in, const int* in_sizes, int n_in,
                              void* d_out, int out_size) {
    const int*   species = (const int*)d_in[0];
    const float* coords  = (const float*)d_in[1];
    float* out = (float*)d_out;

    long long MN = in_sizes[0];                        // M * N
    long long Nm1 = (long long)out_size / (3 * MN);    // out_size = 3*M*N*(N-1)
    int N = (int)Nm1 + 1;
    int M = (int)(MN / N);
    long long P  = (long long)N * (N - 1) / 2;
    long long MP = (long long)M * P;

    int total = (int)MN;
    pack_coords<<<(total + 255) / 256, 256>>>(species, coords, total);

    const float c = 5.2f;
    int R = N - 1;
    int bpm = (R + 1) / 2;       // paired-row blocks per molecule
    int blocks = M * bpm;
    fullpairwise_kernel<<<blocks, 256>>>(out, N, bpm, P, MP, c * c);
}

// round 8
// speedup vs baseline: 1.1671x; 1.0679x over previous
#include <cuda_runtime.h>
#include <stdint.h>

// FullPairwise (non-PBC), output float32 concat:
//   [0    , 2MP)  atom_index12  (row0 = i + m*N, row1 = j + m*N)
//   [2MP  , 5MP)  shift_values  (zeros, [MP,3])
//   [5MP  , 6MP)  mask          (d2 <= cutoff^2 as 0/1; NaN coords -> 0)
// MP = M*P, P = N*(N-1)/2, triu(k=1) row-major pair order.
//
// Fast path (MP%4==0): idx0/idx1/mask share one merged loop per row (3 STG.128
// per iteration, single alignment phase). Zeros region filled flat per block.

#define MAX_ATOMS 16384
__device__ float4 g_coords4[MAX_ATOMS];

__global__ void pack_coords(const int* __restrict__ species,
                            const float* __restrict__ coords, int total) {
    int a = blockIdx.x * blockDim.x + threadIdx.x;
    if (a < total) {
        float x = coords[3 * a + 0];
        float y = coords[3 * a + 1];
        float z = coords[3 * a + 2];
        if (species[a] == -1) {
            x = __int_as_float(0x7fc00000);  // NaN -> mask false (matches ref)
            y = x; z = x;
        }
        g_coords4[a] = make_float4(x, y, z, 0.0f);
    }
}

__device__ __forceinline__ float mask1(float4 ci, float4 cj, float c2) {
    float dx = __fsub_rn(ci.x, cj.x);
    float dy = __fsub_rn(ci.y, cj.y);
    float dz = __fsub_rn(ci.z, cj.z);
    float d2 = __fadd_rn(__fadd_rn(__fmul_rn(dx, dx), __fmul_rn(dy, dy)),
                         __fmul_rn(dz, dz));
    return (d2 <= c2) ? 1.0f : 0.0f;
}

// ---------- fast merged path (requires all 3 regions phase-equal: MP%4==0) ----
__device__ __forceinline__ void do_row_fast(float* __restrict__ out, int m, int i,
                                            int N, long long P, long long MP,
                                            float c2, int tx, int bs) {
    long long rowstart = (long long)i * (N - 1) - ((long long)i * (i - 1)) / 2;
    int L = N - 1 - i;
    long long base = (long long)m * P + rowstart;
    const float4* __restrict__ cm4 = g_coords4 + (size_t)m * N;
    float4 ci = cm4[i];
    int moff = m * N;
    float fi  = (float)(i + moff);
    float fj0 = (float)(i + 1 + moff);

    int h = (int)((4 - (base & 3)) & 3); if (h > L) h = L;
    if (tx < h) {                      // single-shot head (h < 4 <= bs)
        int t = tx;
        out[base + t]          = fi;
        out[MP + base + t]     = fj0 + (float)t;
        out[5 * MP + base + t] = mask1(ci, cm4[i + 1 + t], c2);
    }
    int nv = (L - h) >> 2;
    float4* __restrict__ p0 = (float4*)(out + base + h);
    float4* __restrict__ p1 = (float4*)(out + MP + base + h);
    float4* __restrict__ p3 = (float4*)(out + 5 * MP + base + h);
    float4 v0 = make_float4(fi, fi, fi, fi);
    for (int k = tx; k < nv; k += bs) {
        int j = i + 1 + h + 4 * k;
        float4 c0 = __ldg(cm4 + j);
        float4 c1 = __ldg(cm4 + j + 1);
        float4 cA = __ldg(cm4 + j + 2);
        float4 cB = __ldg(cm4 + j + 3);
        p0[k] = v0;
        float f = fj0 + (float)(h + 4 * k);
        p1[k] = make_float4(f, f + 1.0f, f + 2.0f, f + 3.0f);
        float4 r;
        r.x = mask1(ci, c0, c2);
        r.y = mask1(ci, c1, c2);
        r.z = mask1(ci, cA, c2);
        r.w = mask1(ci, cB, c2);
        p3[k] = r;
    }
    int t = h + 4 * nv + tx;
    if (t < L) {                       // single-shot tail (< 4 elems)
        out[base + t]          = fi;
        out[MP + base + t]     = fj0 + (float)t;
        out[5 * MP + base + t] = mask1(ci, cm4[i + 1 + t], c2);
    }
}

// ---------- generic fallback (arbitrary alignment, per-region loops) ----------
__device__ __forceinline__ void fill_const(float* __restrict__ out, long long b,
                                           int len, float v, int tx, int bs) {
    int h = (int)((4 - (b & 3)) & 3); if (h > len) h = len;
    for (int t = tx; t < h; t += bs) out[b + t] = v;
    int nv = (len - h) >> 2;
    float4* vp = (float4*)(out + b + h);
    float4 v4 = make_float4(v, v, v, v);
    for (int k = tx; k < nv; k += bs) vp[k] = v4;
    for (int t = h + 4 * nv + tx; t < len; t += bs) out[b + t] = v;
}
__device__ __forceinline__ void fill_linear(float* __restrict__ out, long long b,
                                            int len, float f0, int tx, int bs) {
    int h = (int)((4 - (b & 3)) & 3); if (h > len) h = len;
    for (int t = tx; t < h; t += bs) out[b + t] = f0 + (float)t;
    int nv = (len - h) >> 2;
    float4* vp = (float4*)(out + b + h);
    for (int k = tx; k < nv; k += bs) {
        float f = f0 + (float)(h + 4 * k);
        vp[k] = make_float4(f, f + 1.0f, f + 2.0f, f + 3.0f);
    }
    for (int t = h + 4 * nv + tx; t < len; t += bs) out[b + t] = f0 + (float)t;
}
__device__ __forceinline__ void fill_mask(float* __restrict__ out, long long b,
                                          int len, const float4* __restrict__ cm4,
                                          int i, float4 ci, float c2,
                                          int tx, int bs) {
    int h = (int)((4 - (b & 3)) & 3); if (h > len) h = len;
    for (int t = tx; t < h; t += bs) out[b + t] = mask1(ci, cm4[i + 1 + t], c2);
    int nv = (len - h) >> 2;
    float4* vp = (float4*)(out + b + h);
    for (int k = tx; k < nv; k += bs) {
        int j = i + 1 + h + 4 * k;
        float4 c0 = cm4[j], c1 = cm4[j + 1], cA = cm4[j + 2], cB = cm4[j + 3];
        float4 r;
        r.x = mask1(ci, c0, c2); r.y = mask1(ci, c1, c2);
        r.z = mask1(ci, cA, c2); r.w = mask1(ci, cB, c2);
        vp[k] = r;
    }
    for (int t = h + 4 * nv + tx; t < len; t += bs)
        out[b + t] = mask1(ci, cm4[i + 1 + t], c2);
}
__device__ __forceinline__ void do_row_generic(float* __restrict__ out, int m, int i,
                                               int N, long long P, long long MP,
                                               float c2, int tx, int bs) {
    long long rowstart = (long long)i * (N - 1) - ((long long)i * (i - 1)) / 2;
    int L = N - 1 - i;
    long long base = (long long)m * P + rowstart;
    const float4* __restrict__ cm4 = g_coords4 + (size_t)m * N;
    float4 ci = cm4[i];
    int moff = m * N;
    fill_const (out, base,          L, (float)(i + moff),     tx, bs);
    fill_linear(out, MP + base,     L, (float)(i + 1 + moff), tx, bs);
    fill_mask  (out, 5 * MP + base, L, cm4, i, ci, c2,        tx, bs);
}

__global__ void __launch_bounds__(256)
fullpairwise_kernel(float* __restrict__ out,
                    int N, int bpm, long long P, long long MP, float c2,
                    int fast) {
    int bid = blockIdx.x;
    int b = bid % bpm;
    int m = bid / bpm;
    int R = N - 1;
    int r1 = b;
    int r2 = R - 1 - b;
    int tx = threadIdx.x, bs = blockDim.x;

    // ---- flat zeros region: 3MP floats, contiguous aligned slice per block ----
    {
        long long Z = 3 * MP;
        long long g = gridDim.x;
        long long zc = ((Z + g - 1) / g + 3) & ~3LL;   // multiple of 4
        long long s = (long long)bid * zc;
        long long e = s + zc; if (e > Z) e = Z;
        if (s < e) {
            long long zb = 2 * MP + s;
            int len = (int)(e - s);
            int h = (int)((4 - (zb & 3)) & 3); if (h > len) h = len;
            if (tx < h) out[zb + tx] = 0.0f;
            int nv = (len - h) >> 2;
            float4* vp = (float4*)(out + zb + h);
            float4 z4 = make_float4(0.f, 0.f, 0.f, 0.f);
            #pragma unroll 4
            for (int k = tx; k < nv; k += bs) vp[k] = z4;
            int t = h + 4 * nv + tx;
            if (t < len) out[zb + t] = 0.0f;
        }
    }

    if (fast) {
        do_row_fast(out, m, r1, N, P, MP, c2, tx, bs);
        if (r2 > r1) do_row_fast(out, m, r2, N, P, MP, c2, tx, bs);
    } else {
        do_row_generic(out, m, r1, N, P, MP, c2, tx, bs);
        if (r2 > r1) do_row_generic(out, m, r2, N, P, MP, c2, tx, bs);
    }
}

extern "C" void kernel_launch(void* const* d_in, const int* in_sizes, int n_in,
                              void* d_out, int out_size) {
    const int*   species = (const int*)d_in[0];
    const float* coords  = (const float*)d_in[1];
    float* out = (float*)d_out;

    long long MN = in_sizes[0];                        // M * N
    long long Nm1 = (long long)out_size / (3 * MN);    // out_size = 3*M*N*(N-1)
    int N = (int)Nm1 + 1;
    int M = (int)(MN / N);
    long long P  = (long long)N * (N - 1) / 2;
    long long MP = (long long)M * P;

    int total = (int)MN;
    pack_coords<<<(total + 255) / 256, 256>>>(species, coords, total);

    const float c = 5.2f;
    int R = N - 1;
    int bpm = (R + 1) / 2;
    int blocks = M * bpm;
    int fast = (MP % 4 == 0) ? 1 : 0;
    fullpairwise_kernel<<<blocks, 256>>>(out, N, bpm, P, MP, c * c, fast);
}